// round 2
// baseline (speedup 1.0000x reference)
#include <cuda_runtime.h>

// Problem constants
#define NBATCH   512
#define DD       64          // state dim
#define WIDTH    128         // MLP width
#define SSEG     120         // steps per delay segment
#define NSTEPS   600
#define NSAVE    601
#define XDIM     129         // 2*D + 1
#define XP       132         // padded input stride (16B-mult, conflict-free)
#define BT       4           // batch rows per block
#define NTHREADS 128
#define NBLOCKS  (NBATCH / BT)   // 128

// Dopri5 tableau (stage j uses AC[j][0..j-1]); CH = both c_i (time offsets) and
// history interpolation coefficient; BCOEF = solution weights.
__constant__ float AC[6][5] = {
    {0.f, 0.f, 0.f, 0.f, 0.f},
    {0.2f, 0.f, 0.f, 0.f, 0.f},
    {(float)(3.0/40.0), (float)(9.0/40.0), 0.f, 0.f, 0.f},
    {(float)(44.0/45.0), (float)(-56.0/15.0), (float)(32.0/9.0), 0.f, 0.f},
    {(float)(19372.0/6561.0), (float)(-25360.0/2187.0), (float)(64448.0/6561.0),
     (float)(-212.0/729.0), 0.f},
    {(float)(9017.0/3168.0), (float)(-355.0/33.0), (float)(46732.0/5247.0),
     (float)(49.0/176.0), (float)(-5103.0/18656.0)}
};
__constant__ float CH[6] = {0.f, 0.2f, 0.3f, 0.8f, (float)(8.0/9.0), 1.0f};
__constant__ float BCOEF[6] = {(float)(35.0/384.0), 0.f, (float)(500.0/1113.0),
                               (float)(125.0/192.0), (float)(-2187.0/6784.0),
                               (float)(11.0/84.0)};

// ---- packed fp32x2 helpers (Blackwell FFMA2: exact 2x fp32, 2x throughput) ----
__device__ __forceinline__ void fma2(unsigned long long& acc,
                                     unsigned long long w2,
                                     unsigned long long x2) {
    asm("fma.rn.f32x2 %0, %1, %2, %0;" : "+l"(acc) : "l"(w2), "l"(x2));
}
__device__ __forceinline__ unsigned long long pk2(float w) {
    unsigned long long r;
    asm("mov.b64 %0, {%1, %1};" : "=l"(r) : "f"(w));
    return r;
}
__device__ __forceinline__ float2 upk(unsigned long long v) {
    float2 r;
    asm("mov.b64 {%0, %1}, %2;" : "=f"(r.x), "=f"(r.y) : "l"(v));
    return r;
}

// WID-output layer (L1/L2): thread j computes output j for all 4 rows.
// xin: float2[2][XP], pair rp holds rows (2rp, 2rp+1). Weights stride XP, padded 0.
__device__ __forceinline__ void layer_wid(const float* __restrict__ sW,
                                          const float* __restrict__ bias,
                                          const float2* __restrict__ xin,
                                          float2* __restrict__ xout,
                                          int j) {
    unsigned long long a00 = 0ull, a01 = 0ull, a10 = 0ull, a11 = 0ull;
    const float4* w4 = reinterpret_cast<const float4*>(sW + j * XP);
    const ulonglong2* x0 = reinterpret_cast<const ulonglong2*>(xin);
    const ulonglong2* x1 = reinterpret_cast<const ulonglong2*>(xin + XP);
#pragma unroll
    for (int c = 0; c < XP / 4; ++c) {
        float4 w = w4[c];
        ulonglong2 pa0 = x0[2 * c], pb0 = x0[2 * c + 1];
        ulonglong2 pa1 = x1[2 * c], pb1 = x1[2 * c + 1];
        unsigned long long w0 = pk2(w.x);
        fma2(a00, w0, pa0.x); fma2(a10, w0, pa1.x);
        unsigned long long w1 = pk2(w.y);
        fma2(a01, w1, pa0.y); fma2(a11, w1, pa1.y);
        unsigned long long w2p = pk2(w.z);
        fma2(a00, w2p, pb0.x); fma2(a10, w2p, pb1.x);
        unsigned long long w3p = pk2(w.w);
        fma2(a01, w3p, pb0.y); fma2(a11, w3p, pb1.y);
    }
    float2 r0a = upk(a00), r0b = upk(a01), r1a = upk(a10), r1b = upk(a11);
    float b = bias[j];
    float h0 = fmaxf(r0a.x + r0b.x + b, 0.f);
    float h1 = fmaxf(r0a.y + r0b.y + b, 0.f);
    float h2 = fmaxf(r1a.x + r1b.x + b, 0.f);
    float h3 = fmaxf(r1a.y + r1b.y + b, 0.f);
    xout[j]      = make_float2(h0, h1);
    xout[XP + j] = make_float2(h2, h3);
}

// D-output layer (L3): thread (j = tid&63, rp = tid>>6) computes output j for row
// pair rp. No relu. Writes k[4][64].
__device__ __forceinline__ void layer_out(const float* __restrict__ sW3,
                                          const float* __restrict__ sb3,
                                          const float2* __restrict__ xin,
                                          float* __restrict__ kout,
                                          int tid) {
    int j = tid & 63;
    int rp = tid >> 6;
    unsigned long long a0 = 0ull, a1 = 0ull;
    const float4* w4 = reinterpret_cast<const float4*>(sW3 + j * XP);
    const ulonglong2* x = reinterpret_cast<const ulonglong2*>(xin + rp * XP);
#pragma unroll
    for (int c = 0; c < XP / 4; ++c) {
        float4 w = w4[c];
        ulonglong2 pa = x[2 * c], pb = x[2 * c + 1];
        fma2(a0, pk2(w.x), pa.x);
        fma2(a1, pk2(w.y), pa.y);
        fma2(a0, pk2(w.z), pb.x);
        fma2(a1, pk2(w.w), pb.y);
    }
    float2 s0 = upk(a0), s1 = upk(a1);
    float b = sb3[j];
    kout[(2 * rp) * DD + j]     = s0.x + s1.x + b;
    kout[(2 * rp + 1) * DD + j] = s0.y + s1.y + b;
}

// Build stage input x = [y_stage, hist, t] in packed pair layout.
__device__ __forceinline__ void build_x(float2* __restrict__ sx2,
                                        const float* __restrict__ sy,
                                        const float* __restrict__ sk,
                                        int st, float chist,
                                        const float* __restrict__ yp0,
                                        const float* __restrict__ yp1,
                                        float tval, float dtv, int tid) {
    for (int slot = tid; slot < 2 * XDIM; slot += NTHREADS) {
        int rp = slot / XDIM;
        int i  = slot - rp * XDIM;
        int r0 = 2 * rp, r1 = 2 * rp + 1;
        float v0, v1;
        if (i < DD) {
            float s0 = 0.f, s1 = 0.f;
            for (int jj = 0; jj < st; ++jj) {
                float a = AC[st][jj];
                s0 += a * sk[jj * BT * DD + r0 * DD + i];
                s1 += a * sk[jj * BT * DD + r1 * DD + i];
            }
            v0 = sy[r0 * DD + i] + dtv * s0;
            v1 = sy[r1 * DD + i] + dtv * s1;
        } else if (i < 2 * DD) {
            int d = i - DD;
            float p00 = yp0[r0 * DD + d], p01 = yp1[r0 * DD + d];
            float p10 = yp0[r1 * DD + d], p11 = yp1[r1 * DD + d];
            v0 = p00 + chist * (p01 - p00);
            v1 = p10 + chist * (p11 - p10);
        } else {
            v0 = v1 = tval;
        }
        sx2[rp * XP + i] = make_float2(v0, v1);
    }
}

extern __shared__ float smem[];

__global__ __launch_bounds__(NTHREADS, 1)
void dde_kernel(const float* __restrict__ ts, const float* __restrict__ y0,
                const float* __restrict__ W1, const float* __restrict__ b1,
                const float* __restrict__ W2, const float* __restrict__ b2,
                const float* __restrict__ W3, const float* __restrict__ b3,
                float* __restrict__ out, long long out_size) {
    // SMEM layout (floats)
    float* sW1 = smem;                        // WIDTH*XP
    float* sW2 = sW1 + WIDTH * XP;            // WIDTH*XP
    float* sW3 = sW2 + WIDTH * XP;            // DD*XP
    float* sb1 = sW3 + DD * XP;               // WIDTH
    float* sb2 = sb1 + WIDTH;                 // WIDTH
    float* sb3 = sb2 + WIDTH;                 // DD
    float2* sx2 = (float2*)(sb3 + DD);        // 2*XP float2
    float2* sh1 = sx2 + 2 * XP;               // 2*XP float2
    float2* sh2 = sh1 + 2 * XP;               // 2*XP float2
    float* sk   = (float*)(sh2 + 2 * XP);     // 6*BT*DD
    float* sy   = sk + 6 * BT * DD;           // BT*DD
    float* sy0  = sy + BT * DD;               // BT*DD
    float* syp0 = sy0 + BT * DD;              // BT*DD
    float* syp1 = syp0 + BT * DD;             // BT*DD

    const int tid = threadIdx.x;
    const int b0 = blockIdx.x * BT;

    // Zero padded weight buffers + padded activation buffers (pads stay 0 forever).
    for (int i = tid; i < 2 * WIDTH * XP + DD * XP; i += NTHREADS) sW1[i] = 0.f;
    {
        float* sxf = (float*)sx2;
        for (int i = tid; i < 3 * 2 * XP * 2; i += NTHREADS) sxf[i] = 0.f;
    }
    __syncthreads();

    // Load weights (padded stride XP) + biases.
    for (int idx = tid; idx < WIDTH * XDIM; idx += NTHREADS) {
        int j = idx / XDIM, i = idx - j * XDIM;
        sW1[j * XP + i] = W1[idx];
    }
    for (int idx = tid; idx < WIDTH * WIDTH; idx += NTHREADS) {
        int j = idx >> 7, i = idx & 127;
        sW2[j * XP + i] = W2[idx];
    }
    for (int idx = tid; idx < DD * WIDTH; idx += NTHREADS) {
        int j = idx >> 7, i = idx & 127;
        sW3[j * XP + i] = W3[idx];
    }
    for (int i = tid; i < WIDTH; i += NTHREADS) { sb1[i] = b1[i]; sb2[i] = b2[i]; }
    for (int i = tid; i < DD; i += NTHREADS) sb3[i] = b3[i];

    // Initial state + write ys[:,0,:] = y0.
    for (int idx = tid; idx < BT * DD; idx += NTHREADS) {
        int r = idx >> 6, d = idx & 63;
        float v = y0[(size_t)(b0 + r) * DD + d];
        sy[idx] = v;
        sy0[idx] = v;
        out[(size_t)(b0 + r) * NSAVE * DD + d] = v;
    }
    const float ts0 = ts[0];
    const float dtv = ts[1] - ts[0];
    __syncthreads();

#pragma unroll 1
    for (int step = 0; step < NSTEPS; ++step) {
        const float* yp0;
        const float* yp1;
        if (step < SSEG) {
            yp0 = sy0;
            yp1 = sy0;   // constant-history segment: y(t-tau) = y0
        } else {
            // Dense-output lookup: previous-segment grid points step-S, step-S+1
            // (written by this block >=119 steps ago; __syncthreads gives visibility).
            int sel = tid >> 6;       // 0 -> yp0, 1 -> yp1
            int idx = tid & 63;       // float4 slot within [BT][DD]
            int r = idx >> 4, d4 = idx & 15;
            const float4* src = reinterpret_cast<const float4*>(
                out + (size_t)(b0 + r) * NSAVE * DD + (size_t)(step - SSEG + sel) * DD)
                + d4;
            float4 v = *src;
            float4* dst = reinterpret_cast<float4*>(sel ? syp1 : syp0);
            dst[idx] = v;
            yp0 = syp0;
            yp1 = syp1;
            __syncthreads();
        }
        const float tbase = ts0 + (float)step * dtv;

#pragma unroll 1
        for (int st = 0; st < 6; ++st) {
            build_x(sx2, sy, sk, st, CH[st], yp0, yp1, tbase + CH[st] * dtv, dtv, tid);
            __syncthreads();
            layer_wid(sW1, sb1, sx2, sh1, tid);
            __syncthreads();
            layer_wid(sW2, sb2, (const float2*)sh1, sh2, tid);
            __syncthreads();
            layer_out(sW3, sb3, (const float2*)sh2, sk + st * BT * DD, tid);
            __syncthreads();
        }

        // y_{n+1} = y_n + dt * sum_j b_j k_j ; write dense output.
        for (int e = tid; e < BT * DD; e += NTHREADS) {
            float acc = 0.f;
#pragma unroll
            for (int j = 0; j < 6; ++j) acc += BCOEF[j] * sk[j * BT * DD + e];
            float yn = sy[e] + dtv * acc;
            sy[e] = yn;
            int r = e >> 6, d = e & 63;
            out[(size_t)(b0 + r) * NSAVE * DD + (size_t)(step + 1) * DD + d] = yn;
        }
        __syncthreads();
    }

    // num_steps (int 600 cast to output dtype) appended after ys.
    if (blockIdx.x == 0) {
        long long yssz = (long long)NBATCH * NSAVE * DD;
        for (long long i = yssz + tid; i < out_size; i += NTHREADS) out[i] = 600.0f;
    }
}

#define SMEM_FLOATS (2 * WIDTH * XP + DD * XP + 2 * WIDTH + DD \
                     + 3 * 2 * XP * 2 + 6 * BT * DD + 4 * BT * DD)

extern "C" void kernel_launch(void* const* d_in, const int* in_sizes, int n_in,
                              void* d_out, int out_size) {
    const float* ts = (const float*)d_in[0];
    const float* y0 = (const float*)d_in[1];
    const float* W1 = (const float*)d_in[2];
    const float* b1 = (const float*)d_in[3];
    const float* W2 = (const float*)d_in[4];
    const float* b2 = (const float*)d_in[5];
    const float* W3 = (const float*)d_in[6];
    const float* b3 = (const float*)d_in[7];
    float* out = (float*)d_out;

    size_t smem_bytes = (size_t)SMEM_FLOATS * sizeof(float);
    cudaFuncSetAttribute(dde_kernel, cudaFuncAttributeMaxDynamicSharedMemorySize,
                         (int)smem_bytes);

    dde_kernel<<<NBLOCKS, NTHREADS, smem_bytes>>>(ts, y0, W1, b1, W2, b2, W3, b3,
                                                  out, (long long)out_size);
}